// round 11
// baseline (speedup 1.0000x reference)
#include <cuda_runtime.h>
#include <cstdint>

// SequentialLoraA — adapter-major TMA-streaming formulation.
//   y_large[b,r] = sum_d x[b,d]     * A_large[wids_large[b], d, r]   (r<64)
//   y_small[b,r] = sum_d x[256+b,d] * A_small[wids_small[b], d, r]   (r<16)
// All f16 tensors arrive as FLOAT32. Output f32: y_large (256*64) then
// y_small (256*16).
//
// prep:   bucket samples by adapter id (device lists, rebuilt every call).
// stream: grid = 128*4 large (adapter, d-quarter) CTAs + 128 small adapter
//         CTAs. Each streams its contiguous 256KB adapter chunk ONCE via
//         cp.async.bulk (16KB tiles, double-buffered smem, mbarrier), FMAing
//         against up to GROUP samples per pass. Large partials -> scratch.
// reduce: y_large[b] = sum over 4 d-quarter partials.

#define D_DIM    4096
#define B_LARGE  256
#define B_SMALL  256
#define R_LARGE  64
#define R_SMALL  16
#define N_ADAPT  128
#define GROUP    4
#define TILE_BYTES 16384
#define N_TILES    16          // 256 KB / 16 KB

__device__ int g_cnt_l[N_ADAPT];
__device__ int g_cnt_s[N_ADAPT];
__device__ int g_list_l[N_ADAPT][B_LARGE];
__device__ int g_list_s[N_ADAPT][B_SMALL];
__device__ float g_scratch[B_LARGE][4][R_LARGE];   // large partials per d-quarter

__global__ void prep_kernel(const int* __restrict__ wl,
                            const int* __restrict__ ws)
{
    const int t = threadIdx.x;      // 256 threads
    if (t < N_ADAPT) { g_cnt_l[t] = 0; g_cnt_s[t] = 0; }
    __syncthreads();
    { const int w = wl[t]; g_list_l[w][atomicAdd(&g_cnt_l[w], 1)] = t; }
    { const int w = ws[t]; g_list_s[w][atomicAdd(&g_cnt_s[w], 1)] = t; }
}

__device__ __forceinline__ uint32_t smem_u32(const void* p) {
    uint32_t a;
    asm("{ .reg .u64 t; cvta.to.shared.u64 t, %1; cvt.u32.u64 %0, t; }"
        : "=r"(a) : "l"(p));
    return a;
}

#define MBAR_INIT(a, c) \
    asm volatile("mbarrier.init.shared.b64 [%0], %1;" :: "r"(a), "r"(c) : "memory")
#define MBAR_EXPECT(a, b) \
    asm volatile("mbarrier.arrive.expect_tx.shared.b64 _, [%0], %1;" :: "r"(a), "r"(b) : "memory")
#define BULK1D(dst, src, nbytes, mbar) \
    asm volatile("cp.async.bulk.shared::cluster.global.mbarrier::complete_tx::bytes [%0], [%1], %2, [%3];" \
                 :: "r"(dst), "l"(src), "r"(nbytes), "r"(mbar) : "memory")
#define FENCE_ASYNC() asm volatile("fence.proxy.async.shared::cta;" ::: "memory")

__device__ __forceinline__ void mbar_wait(uint32_t mbar, uint32_t parity) {
    asm volatile(
        "{\n\t"
        ".reg .pred P;\n\t"
        "WL_%=:\n\t"
        "mbarrier.try_wait.parity.acquire.cta.shared::cta.b64 P, [%0], %1, 0x989680;\n\t"
        "@P bra.uni WD_%=;\n\t"
        "bra.uni WL_%=;\n\t"
        "WD_%=:\n\t"
        "}" :: "r"(mbar), "r"(parity) : "memory");
}

// smem layout (static, 41 KB):
//   [0, 32768)      bufA[2][4096 floats]    (reused as wsum in epilogue)
//   [32768, 40960)  xbuf[2][GROUP*256 floats]
//   [40960, 40976)  mbar[2]
__shared__ __align__(128) char s_raw[32768 + 8192 + 16];

__global__ __launch_bounds__(256)
void lora_stream_kernel(const float* __restrict__ x,
                        const float* __restrict__ A_large,
                        const float* __restrict__ A_small,
                        float*       __restrict__ out)
{
    float* bufA = (float*)s_raw;                 // 2 x 4096 floats
    float* xbuf = (float*)(s_raw + 32768);       // 2 x 1024 floats
    const uint32_t mb0 = smem_u32(s_raw + 40960);
    const uint32_t mb1 = mb0 + 8;
    const uint32_t bufA_u32 = smem_u32(s_raw);

    const int c    = blockIdx.x;                 // 0..639
    const int tid  = threadIdx.x;
    const int warp = tid >> 5;
    const int lane = tid & 31;

    const bool is_large = (c < N_ADAPT * 4);
    int w, q = 0, cnt;
    const int* list;
    const float* src;

    if (is_large) {
        w    = c >> 2;
        q    = c & 3;
        cnt  = g_cnt_l[w];
        list = g_list_l[w];
        src  = A_large + (size_t)w * D_DIM * R_LARGE + (size_t)q * 1024 * R_LARGE;
    } else {
        w    = c - N_ADAPT * 4;
        cnt  = g_cnt_s[w];
        list = g_list_s[w];
        src  = A_small + (size_t)w * D_DIM * R_SMALL;
    }
    if (cnt == 0) return;

    if (tid == 0) { MBAR_INIT(mb0, 1); MBAR_INIT(mb1, 1); }
    __syncthreads();

    int ph0 = 0, ph1 = 0;

    for (int g = 0; g < cnt; g += GROUP) {
        const int gcnt = min(GROUP, cnt - g);
        int bidx[GROUP];
        #pragma unroll
        for (int s = 0; s < GROUP; ++s) bidx[s] = (s < gcnt) ? list[g + s] : 0;

        // issue tiles 0 and 1
        if (tid == 0) {
            FENCE_ASYNC();   // order prior generic smem writes vs async writes
            MBAR_EXPECT(mb0, TILE_BYTES);
            BULK1D(bufA_u32, src, TILE_BYTES, mb0);
            MBAR_EXPECT(mb1, TILE_BYTES);
            BULK1D(bufA_u32 + TILE_BYTES, (const char*)src + TILE_BYTES,
                   TILE_BYTES, mb1);
        }

        // accumulators
        float2 accL[GROUP];     // large: per (sample, col pair = lane)
        float  accS[GROUP];     // small: per (sample, col = lane&15)
        #pragma unroll
        for (int s = 0; s < GROUP; ++s) { accL[s] = make_float2(0.f, 0.f); accS[s] = 0.f; }

        for (int t = 0; t < N_TILES; ++t) {
            const int cur = t & 1;
            float* bA = bufA + cur * 4096;
            float* bX = xbuf + cur * (GROUP * 256);

            // stage x tile for this A tile (zeros for unused slots)
            if (is_large) {
                // 64 rows per tile: 256 floats total
                const int s = tid >> 6, row = tid & 63;
                float v = 0.f;
                if (s < gcnt)
                    v = x[(size_t)bidx[s] * D_DIM + q * 1024 + t * 64 + row];
                bX[s * 64 + row] = v;
            } else {
                // 256 rows per tile: 1024 floats total
                #pragma unroll
                for (int k = 0; k < 4; ++k) {
                    const int i = tid + k * 256;
                    const int s = i >> 8, row = i & 255;
                    float v = 0.f;
                    if (s < gcnt)
                        v = x[(size_t)(B_LARGE + bidx[s]) * D_DIM + t * 256 + row];
                    bX[s * 256 + row] = v;
                }
            }

            // wait for A tile
            if (cur == 0) { mbar_wait(mb0, ph0); ph0 ^= 1; }
            else          { mbar_wait(mb1, ph1); ph1 ^= 1; }
            __syncthreads();                     // xbuf visible to all

            if (is_large) {
                // tile: 64 rows x 64 cols. warp owns 8 rows; lane owns col pair.
                #pragma unroll
                for (int r = 0; r < 8; ++r) {
                    const int row = warp * 8 + r;
                    const float2 v = *(const float2*)(bA + row * 64 + lane * 2);
                    #pragma unroll
                    for (int s = 0; s < GROUP; ++s) {
                        const float xs = bX[s * 64 + row];
                        accL[s].x = fmaf(xs, v.x, accL[s].x);
                        accL[s].y = fmaf(xs, v.y, accL[s].y);
                    }
                }
            } else {
                // tile: 256 rows x 16 cols. warp owns 32 rows; lane: col = lane&15,
                // half = lane>>4 covers 16 of the 32 rows.
                const int colS = lane & 15;
                const int rbase = warp * 32 + (lane >> 4) * 16;
                #pragma unroll
                for (int r = 0; r < 16; ++r) {
                    const int row = rbase + r;
                    const float v = bA[row * 16 + colS];
                    #pragma unroll
                    for (int s = 0; s < GROUP; ++s)
                        accS[s] = fmaf(bX[s * 256 + row], v, accS[s]);
                }
            }
            __syncthreads();                     // tile fully consumed

            // refill this buffer with tile t+2
            if (tid == 0 && t + 2 < N_TILES) {
                const uint32_t dst = bufA_u32 + cur * TILE_BYTES;
                const char* s2 = (const char*)src + (size_t)(t + 2) * TILE_BYTES;
                if (cur == 0) { MBAR_EXPECT(mb0, TILE_BYTES); BULK1D(dst, s2, TILE_BYTES, mb0); }
                else          { MBAR_EXPECT(mb1, TILE_BYTES); BULK1D(dst, s2, TILE_BYTES, mb1); }
            }
        }

        // ---- epilogue: cross-warp reduce (reuse bufA as wsum) ----
        __syncthreads();
        float* wsum = bufA;   // large: [8][GROUP][64]; small: [8][GROUP][16]
        if (is_large) {
            #pragma unroll
            for (int s = 0; s < GROUP; ++s) {
                wsum[(warp * GROUP + s) * 64 + lane * 2]     = accL[s].x;
                wsum[(warp * GROUP + s) * 64 + lane * 2 + 1] = accL[s].y;
            }
        } else {
            #pragma unroll
            for (int s = 0; s < GROUP; ++s) {
                float v = accS[s];
                v += __shfl_xor_sync(0xffffffffu, v, 16);   // combine row halves
                if (lane < 16) wsum[(warp * GROUP + s) * 16 + lane] = v;
            }
        }
        __syncthreads();

        if (is_large) {
            const int s = tid >> 6, col = tid & 63;     // 256 threads cover all
            if (s < gcnt) {
                float sum = 0.f;
                #pragma unroll
                for (int ww = 0; ww < 8; ++ww) sum += wsum[(ww * GROUP + s) * 64 + col];
                g_scratch[bidx[s]][q][col] = sum;
            }
        } else {
            if (tid < gcnt * 16) {
                const int s = tid >> 4, r = tid & 15;
                float sum = 0.f;
                #pragma unroll
                for (int ww = 0; ww < 8; ++ww) sum += wsum[(ww * GROUP + s) * 16 + r];
                out[B_LARGE * R_LARGE + bidx[s] * R_SMALL + r] = sum;
            }
        }
        __syncthreads();    // wsum reads done before next pass reuses bufA
    }
}

__global__ void reduce_kernel(float* __restrict__ out)
{
    const int i = blockIdx.x * 256 + threadIdx.x;   // 0..16383
    const int b = i >> 6, col = i & 63;
    float s = 0.f;
    #pragma unroll
    for (int q = 0; q < 4; ++q) s += g_scratch[b][q][col];
    out[b * R_LARGE + col] = s;
}

extern "C" void kernel_launch(void* const* d_in, const int* in_sizes, int n_in,
                              void* d_out, int out_size)
{
    const float* x      = nullptr;
    const float* Alarge = nullptr;
    const float* Asmall = nullptr;
    const int*   widl   = nullptr;
    const int*   widsm  = nullptr;

    for (int i = 0; i < n_in; ++i) {
        const int sz = in_sizes[i];
        if (sz == 512 * D_DIM)                    x      = (const float*)d_in[i];
        else if (sz == 128 * D_DIM * R_LARGE)     Alarge = (const float*)d_in[i];
        else if (sz == 128 * D_DIM * R_SMALL)     Asmall = (const float*)d_in[i];
        else if (sz == 256) { if (!widl) widl = (const int*)d_in[i];
                              else       widsm = (const int*)d_in[i]; }
    }

    float* out = (float*)d_out;
    prep_kernel<<<1, 256>>>(widl, widsm);
    lora_stream_kernel<<<N_ADAPT * 4 + N_ADAPT, 256>>>(x, Alarge, Asmall, out);
    reduce_kernel<<<64, 256>>>(out);
}

// round 12
// speedup vs baseline: 1.2824x; 1.2824x over previous
#include <cuda_runtime.h>

// SequentialLoraA — adapter-major, single-kernel formulation.
//   y_large[b,r] = sum_d x[b,d]     * A_large[wids_large[b], d, r]   (r<64)
//   y_small[b,r] = sum_d x[256+b,d] * A_small[wids_small[b], d, r]   (r<16)
// All f16 tensors arrive as FLOAT32. Output f32: y_large (256*64) then
// y_small (256*16).
//
// Grid = 128*4 large (adapter, 16-col chunk) CTAs + 128 small adapter CTAs.
// Each CTA scans the 1KB wid array to find its samples (no serial prep
// kernel), then streams its 256KB adapter chunk once per pass, with
// pass width specialized to the actual multiplicity (G in {1,2,4}).

#define D_DIM    4096
#define B_LARGE  256
#define B_SMALL  256
#define R_LARGE  64
#define R_SMALL  16
#define N_ADAPT  128

// Unified geometry (both paths): CTA owns 16 output columns over full d.
// Per warp-iter: 8 rows (rowsub = lane>>2) x 16 cols (col = (lane&3)*4).
// Per d-tile of 1024 rows: warp covers rows [warp*128, warp*128+128), 16 iters.

template<int G>
__device__ __forceinline__ void do_pass(
    bool is_large, const float* __restrict__ A, const float* __restrict__ x,
    const int* bidx, int gcnt, int rc,
    float* __restrict__ sxs, float* __restrict__ wsum,
    float* __restrict__ out, int warp, int lane, int tid)
{
    const int stride = is_large ? R_LARGE : R_SMALL;
    const int col    = (lane & 3) * 4;
    const int rowsub = lane >> 2;
    const int dbase  = warp * 128 + rowsub;

    float4 acc[G];
    #pragma unroll
    for (int s = 0; s < G; ++s) acc[s] = make_float4(0.f, 0.f, 0.f, 0.f);

    for (int t = 0; t < 4; ++t) {          // d-tiles of 1024
        __syncthreads();                   // previous tile fully consumed
        // stage x tiles for the group (zeros for padded slots)
        for (int i = tid; i < G * 256; i += 256) {
            const int s = i >> 8, j = i & 255;
            float4 v = make_float4(0.f, 0.f, 0.f, 0.f);
            if (s < gcnt) {
                const int b  = bidx[s];
                const int xb = is_large ? b : (B_LARGE + b);
                v = ((const float4*)(x + (size_t)xb * D_DIM + t * 1024))[j];
            }
            ((float4*)sxs)[s * 256 + j] = v;
        }
        __syncthreads();

        const float* At = A + (size_t)t * 1024 * stride;
        #pragma unroll 4
        for (int it = 0; it < 16; ++it) {
            const int d = dbase + it * 8;
            const float4 v = *(const float4*)(At + (size_t)d * stride + col);
            #pragma unroll
            for (int s = 0; s < G; ++s) {
                const float xs = sxs[s * 1024 + d];
                acc[s].x = fmaf(xs, v.x, acc[s].x);
                acc[s].y = fmaf(xs, v.y, acc[s].y);
                acc[s].z = fmaf(xs, v.z, acc[s].z);
                acc[s].w = fmaf(xs, v.w, acc[s].w);
            }
        }
    }

    // reduce over the 8 row-groups (lane bits 2..4)
    #pragma unroll
    for (int s = 0; s < G; ++s) {
        #pragma unroll
        for (int m = 4; m <= 16; m <<= 1) {
            acc[s].x += __shfl_xor_sync(0xffffffffu, acc[s].x, m);
            acc[s].y += __shfl_xor_sync(0xffffffffu, acc[s].y, m);
            acc[s].z += __shfl_xor_sync(0xffffffffu, acc[s].z, m);
            acc[s].w += __shfl_xor_sync(0xffffffffu, acc[s].w, m);
        }
    }
    __syncthreads();
    if (lane < 4) {
        #pragma unroll
        for (int s = 0; s < G; ++s) {
            wsum[(warp * G + s) * 16 + col + 0] = acc[s].x;
            wsum[(warp * G + s) * 16 + col + 1] = acc[s].y;
            wsum[(warp * G + s) * 16 + col + 2] = acc[s].z;
            wsum[(warp * G + s) * 16 + col + 3] = acc[s].w;
        }
    }
    __syncthreads();

    if (tid < gcnt * 16) {
        const int s = tid >> 4, r = tid & 15;
        float sum = 0.f;
        #pragma unroll
        for (int ww = 0; ww < 8; ++ww) sum += wsum[(ww * G + s) * 16 + r];
        const int b = bidx[s];
        if (is_large) out[b * R_LARGE + rc + r] = sum;
        else          out[B_LARGE * R_LARGE + b * R_SMALL + r] = sum;
    }
    __syncthreads();                       // wsum/sxs free for next pass
}

__global__ __launch_bounds__(256, 4)
void lora_kernel(const float* __restrict__ x,
                 const int*   __restrict__ wl,
                 const int*   __restrict__ ws,
                 const float* __restrict__ A_large,
                 const float* __restrict__ A_small,
                 float*       __restrict__ out)
{
    __shared__ float sxs[4 * 1024];     // 16 KB: x tiles (G<=4 samples)
    __shared__ float wsum[8 * 4 * 16];  // 2 KB: per-warp partials
    __shared__ int   s_list[256];
    __shared__ int   s_cnt;

    const int c    = blockIdx.x;        // 0..639
    const int tid  = threadIdx.x;       // 0..255
    const int warp = tid >> 5;
    const int lane = tid & 31;

    const bool is_large = (c < N_ADAPT * 4);
    int w, rc = 0;
    const float* A;
    if (is_large) {
        w  = c >> 2;
        rc = (c & 3) * 16;
        A  = A_large + (size_t)w * D_DIM * R_LARGE + rc;
    } else {
        w = c - N_ADAPT * 4;
        A = A_small + (size_t)w * D_DIM * R_SMALL;
    }

    // ---- inline bucketing: find samples using adapter w ----
    if (tid == 0) s_cnt = 0;
    __syncthreads();
    const int wv = is_large ? wl[tid] : ws[tid];
    if (wv == w) s_list[atomicAdd(&s_cnt, 1)] = tid;
    __syncthreads();
    const int cnt = s_cnt;
    if (cnt == 0) return;               // unused adapter: no streaming

    int g = 0;
    while (g < cnt) {
        const int rem = cnt - g;
        int bidx[4];
        const int take = (rem >= 3) ? ((rem >= 4) ? 4 : 3) : rem;
        #pragma unroll
        for (int s = 0; s < 4; ++s) bidx[s] = (s < take) ? s_list[g + s] : 0;

        if (rem >= 3) {
            do_pass<4>(is_large, A, x, bidx, take, rc, sxs, wsum, out, warp, lane, tid);
        } else if (rem == 2) {
            do_pass<2>(is_large, A, x, bidx, 2, rc, sxs, wsum, out, warp, lane, tid);
        } else {
            do_pass<1>(is_large, A, x, bidx, 1, rc, sxs, wsum, out, warp, lane, tid);
        }
        g += take;
    }
}

extern "C" void kernel_launch(void* const* d_in, const int* in_sizes, int n_in,
                              void* d_out, int out_size)
{
    const float* x      = nullptr;
    const float* Alarge = nullptr;
    const float* Asmall = nullptr;
    const int*   widl   = nullptr;
    const int*   widsm  = nullptr;

    for (int i = 0; i < n_in; ++i) {
        const int sz = in_sizes[i];
        if (sz == 512 * D_DIM)                x      = (const float*)d_in[i];
        else if (sz == 128 * D_DIM * R_LARGE) Alarge = (const float*)d_in[i];
        else if (sz == 128 * D_DIM * R_SMALL) Asmall = (const float*)d_in[i];
        else if (sz == 256) { if (!widl) widl = (const int*)d_in[i];
                              else       widsm = (const int*)d_in[i]; }
    }

    float* out = (float*)d_out;
    lora_kernel<<<N_ADAPT * 4 + N_ADAPT, 256>>>(x, widl, widsm, Alarge, Asmall, out);
}

// round 13
// speedup vs baseline: 1.4097x; 1.0992x over previous
#include <cuda_runtime.h>

// SequentialLoraA — adapter-major, single-kernel, deep-MLP inner loop.
//   y_large[b,r] = sum_d x[b,d]     * A_large[wids_large[b], d, r]   (r<64)
//   y_small[b,r] = sum_d x[256+b,d] * A_small[wids_small[b], d, r]   (r<16)
// All f16 tensors arrive as FLOAT32. Output f32: y_large (256*64) then
// y_small (256*16).
//
// Grid = 128*4 large (adapter, 16-col chunk) CTAs + 128 small adapter CTAs.
// Each CTA scans the 1KB wid array to find its samples, then streams its
// 256KB adapter chunk once per pass (pass width G in {1,2,4} by multiplicity).
// Inner loop batches 8 LDG.128 into registers before the FMA drain to double
// per-warp memory-level parallelism (the binding resource per the B300 LDG
// latency model).

#define D_DIM    4096
#define B_LARGE  256
#define B_SMALL  256
#define R_LARGE  64
#define R_SMALL  16
#define N_ADAPT  128

// Geometry: CTA owns 16 output columns over full d.
// Per warp-step: 8 rows (rowsub = lane>>2) x 16 cols (col = (lane&3)*4).
// d-tile of 1024 rows: warp covers rows [warp*128, warp*128+128) in 16 steps,
// executed as 2 blocks of 8 batched steps.

template<int G>
__device__ __forceinline__ void do_pass(
    bool is_large, const float* __restrict__ A, const float* __restrict__ x,
    const int* bidx, int gcnt, int rc,
    float* __restrict__ sxs, float* __restrict__ wsum,
    float* __restrict__ out, int warp, int lane, int tid)
{
    const int stride = is_large ? R_LARGE : R_SMALL;
    const int col    = (lane & 3) * 4;
    const int rowsub = lane >> 2;
    const int dbase  = warp * 128 + rowsub;

    float4 acc[G];
    #pragma unroll
    for (int s = 0; s < G; ++s) acc[s] = make_float4(0.f, 0.f, 0.f, 0.f);

    for (int t = 0; t < 4; ++t) {          // d-tiles of 1024
        __syncthreads();                   // previous tile fully consumed
        // stage x tiles for the group (zeros for padded slots)
        for (int i = tid; i < G * 256; i += 256) {
            const int s = i >> 8, j = i & 255;
            float4 v = make_float4(0.f, 0.f, 0.f, 0.f);
            if (s < gcnt) {
                const int b  = bidx[s];
                const int xb = is_large ? b : (B_LARGE + b);
                v = ((const float4*)(x + (size_t)xb * D_DIM + t * 1024))[j];
            }
            ((float4*)sxs)[s * 256 + j] = v;
        }
        __syncthreads();

        const float* At = A + (size_t)t * 1024 * stride;

        #pragma unroll
        for (int blk = 0; blk < 2; ++blk) {
            // ---- batch 8 back-to-back LDG.128 (MLP_p1 = 8) ----
            float4 v[8];
            #pragma unroll
            for (int j = 0; j < 8; ++j) {
                const int d = dbase + (blk * 8 + j) * 8;
                v[j] = *(const float4*)(At + (size_t)d * stride + col);
            }
            // ---- drain: FMA against staged x ----
            #pragma unroll
            for (int j = 0; j < 8; ++j) {
                const int d = dbase + (blk * 8 + j) * 8;
                #pragma unroll
                for (int s = 0; s < G; ++s) {
                    const float xs = sxs[s * 1024 + d];
                    acc[s].x = fmaf(xs, v[j].x, acc[s].x);
                    acc[s].y = fmaf(xs, v[j].y, acc[s].y);
                    acc[s].z = fmaf(xs, v[j].z, acc[s].z);
                    acc[s].w = fmaf(xs, v[j].w, acc[s].w);
                }
            }
        }
    }

    // reduce over the 8 row-groups (lane bits 2..4)
    #pragma unroll
    for (int s = 0; s < G; ++s) {
        #pragma unroll
        for (int m = 4; m <= 16; m <<= 1) {
            acc[s].x += __shfl_xor_sync(0xffffffffu, acc[s].x, m);
            acc[s].y += __shfl_xor_sync(0xffffffffu, acc[s].y, m);
            acc[s].z += __shfl_xor_sync(0xffffffffu, acc[s].z, m);
            acc[s].w += __shfl_xor_sync(0xffffffffu, acc[s].w, m);
        }
    }
    __syncthreads();
    if (lane < 4) {
        #pragma unroll
        for (int s = 0; s < G; ++s) {
            wsum[(warp * G + s) * 16 + col + 0] = acc[s].x;
            wsum[(warp * G + s) * 16 + col + 1] = acc[s].y;
            wsum[(warp * G + s) * 16 + col + 2] = acc[s].z;
            wsum[(warp * G + s) * 16 + col + 3] = acc[s].w;
        }
    }
    __syncthreads();

    if (tid < gcnt * 16) {
        const int s = tid >> 4, r = tid & 15;
        float sum = 0.f;
        #pragma unroll
        for (int ww = 0; ww < 8; ++ww) sum += wsum[(ww * G + s) * 16 + r];
        const int b = bidx[s];
        if (is_large) out[b * R_LARGE + rc + r] = sum;
        else          out[B_LARGE * R_LARGE + b * R_SMALL + r] = sum;
    }
    __syncthreads();                       // wsum/sxs free for next pass
}

__global__ __launch_bounds__(256, 3)
void lora_kernel(const float* __restrict__ x,
                 const int*   __restrict__ wl,
                 const int*   __restrict__ ws,
                 const float* __restrict__ A_large,
                 const float* __restrict__ A_small,
                 float*       __restrict__ out)
{
    __shared__ float sxs[4 * 1024];     // 16 KB: x tiles (G<=4 samples)
    __shared__ float wsum[8 * 4 * 16];  // 2 KB: per-warp partials
    __shared__ int   s_list[256];
    __shared__ int   s_cnt;

    const int c    = blockIdx.x;        // 0..639
    const int tid  = threadIdx.x;       // 0..255
    const int warp = tid >> 5;
    const int lane = tid & 31;

    const bool is_large = (c < N_ADAPT * 4);
    int w, rc = 0;
    const float* A;
    if (is_large) {
        w  = c >> 2;
        rc = (c & 3) * 16;
        A  = A_large + (size_t)w * D_DIM * R_LARGE + rc;
    } else {
        w = c - N_ADAPT * 4;
        A = A_small + (size_t)w * D_DIM * R_SMALL;
    }

    // ---- inline bucketing: find samples using adapter w ----
    if (tid == 0) s_cnt = 0;
    __syncthreads();
    const int wv = is_large ? wl[tid] : ws[tid];
    if (wv == w) s_list[atomicAdd(&s_cnt, 1)] = tid;
    __syncthreads();
    const int cnt = s_cnt;
    if (cnt == 0) return;               // unused adapter: no streaming

    int g = 0;
    while (g < cnt) {
        const int rem = cnt - g;
        int bidx[4];
        const int take = (rem >= 3) ? ((rem >= 4) ? 4 : 3) : rem;
        #pragma unroll
        for (int s = 0; s < 4; ++s) bidx[s] = (s < take) ? s_list[g + s] : 0;

        if (rem >= 3) {
            do_pass<4>(is_large, A, x, bidx, take, rc, sxs, wsum, out, warp, lane, tid);
        } else if (rem == 2) {
            do_pass<2>(is_large, A, x, bidx, 2, rc, sxs, wsum, out, warp, lane, tid);
        } else {
            do_pass<1>(is_large, A, x, bidx, 1, rc, sxs, wsum, out, warp, lane, tid);
        }
        g += take;
    }
}

extern "C" void kernel_launch(void* const* d_in, const int* in_sizes, int n_in,
                              void* d_out, int out_size)
{
    const float* x      = nullptr;
    const float* Alarge = nullptr;
    const float* Asmall = nullptr;
    const int*   widl   = nullptr;
    const int*   widsm  = nullptr;

    for (int i = 0; i < n_in; ++i) {
        const int sz = in_sizes[i];
        if (sz == 512 * D_DIM)                x      = (const float*)d_in[i];
        else if (sz == 128 * D_DIM * R_LARGE) Alarge = (const float*)d_in[i];
        else if (sz == 128 * D_DIM * R_SMALL) Asmall = (const float*)d_in[i];
        else if (sz == 256) { if (!widl) widl = (const int*)d_in[i];
                              else       widsm = (const int*)d_in[i]; }
    }

    float* out = (float*)d_out;
    lora_kernel<<<N_ADAPT * 4 + N_ADAPT, 256>>>(x, widl, widsm, Alarge, Asmall, out);
}

// round 15
// speedup vs baseline: 1.4786x; 1.0489x over previous
#include <cuda_runtime.h>
#include <cstdint>

// SequentialLoraA — adapter-major, barrier-free streaming mainloop.
//   y_large[b,r] = sum_d x[b,d]     * A_large[wids_large[b], d, r]   (r<64)
//   y_small[b,r] = sum_d x[256+b,d] * A_small[wids_small[b], d, r]   (r<16)
// All f16 tensors arrive as FLOAT32. Output f32: y_large (256*64) then
// y_small (256*16).
//
// Grid = 128*4 large (adapter, 16-col chunk) CTAs + 128 small adapter CTAs.
// Each CTA scans the 1KB wid array inline to find its samples, then streams
// its 256KB adapter chunk once per pass (G in {1,2,4} by multiplicity).
// Mainloop: 8-deep batched LDG.128 (L1::no_allocate, A never pollutes L1),
// x read via __ldg (L1-resident 16KB rows). NO barriers inside the stream —
// the load pipeline never drains.

#define D_DIM    4096
#define B_LARGE  256
#define B_SMALL  256
#define R_LARGE  64
#define R_SMALL  16
#define N_ADAPT  128

__device__ __forceinline__ float4 ldg_stream(const float* p) {
    float4 v;
    asm volatile("ld.global.nc.L1::no_allocate.v4.f32 {%0,%1,%2,%3}, [%4];"
                 : "=f"(v.x), "=f"(v.y), "=f"(v.z), "=f"(v.w) : "l"(p));
    return v;
}

// Geometry: CTA owns 16 output columns over full d (4096 rows).
// Per warp-step: 8 rows (rowsub = lane>>2) x 16 cols (col = (lane&3)*4).
// Warp covers d in [warp*512, warp*512+512): 64 steps = 8 blocks x 8 batched.

template<int G>
__device__ __forceinline__ void do_pass(
    bool is_large, const float* __restrict__ A, const float* __restrict__ x,
    const int* bidx, int gcnt, int rc,
    float* __restrict__ wsum, float* __restrict__ out,
    int warp, int lane, int tid)
{
    const int stride = is_large ? R_LARGE : R_SMALL;
    const int col    = (lane & 3) * 4;
    const int rowsub = lane >> 2;
    const int dbase  = warp * 512 + rowsub;

    // per-sample x row base pointers (padded slots alias slot 0; acc unused)
    const float* xp[G];
    #pragma unroll
    for (int s = 0; s < G; ++s) {
        const int b  = bidx[(s < gcnt) ? s : 0];
        const int xb = is_large ? b : (B_LARGE + b);
        xp[s] = x + (size_t)xb * D_DIM;
    }

    float4 acc[G];
    #pragma unroll
    for (int s = 0; s < G; ++s) acc[s] = make_float4(0.f, 0.f, 0.f, 0.f);

    for (int blk = 0; blk < 8; ++blk) {
        // ---- 8 back-to-back streaming LDG.128 (no L1 allocate) ----
        float4 v[8];
        #pragma unroll
        for (int j = 0; j < 8; ++j) {
            const int d = dbase + (blk * 8 + j) * 8;
            v[j] = ldg_stream(A + (size_t)d * stride + col);
        }
        // ---- drain: FMA against L1-resident x ----
        #pragma unroll
        for (int j = 0; j < 8; ++j) {
            const int d = dbase + (blk * 8 + j) * 8;
            #pragma unroll
            for (int s = 0; s < G; ++s) {
                const float xs = __ldg(xp[s] + d);
                acc[s].x = fmaf(xs, v[j].x, acc[s].x);
                acc[s].y = fmaf(xs, v[j].y, acc[s].y);
                acc[s].z = fmaf(xs, v[j].z, acc[s].z);
                acc[s].w = fmaf(xs, v[j].w, acc[s].w);
            }
        }
    }

    // reduce over the 8 row-groups (lane bits 2..4)
    #pragma unroll
    for (int s = 0; s < G; ++s) {
        #pragma unroll
        for (int m = 4; m <= 16; m <<= 1) {
            acc[s].x += __shfl_xor_sync(0xffffffffu, acc[s].x, m);
            acc[s].y += __shfl_xor_sync(0xffffffffu, acc[s].y, m);
            acc[s].z += __shfl_xor_sync(0xffffffffu, acc[s].z, m);
            acc[s].w += __shfl_xor_sync(0xffffffffu, acc[s].w, m);
        }
    }
    __syncthreads();
    if (lane < 4) {
        #pragma unroll
        for (int s = 0; s < G; ++s) {
            wsum[(warp * G + s) * 16 + col + 0] = acc[s].x;
            wsum[(warp * G + s) * 16 + col + 1] = acc[s].y;
            wsum[(warp * G + s) * 16 + col + 2] = acc[s].z;
            wsum[(warp * G + s) * 16 + col + 3] = acc[s].w;
        }
    }
    __syncthreads();

    if (tid < gcnt * 16) {
        const int s = tid >> 4, r = tid & 15;
        float sum = 0.f;
        #pragma unroll
        for (int ww = 0; ww < 8; ++ww) sum += wsum[(ww * G + s) * 16 + r];
        const int b = bidx[s];
        if (is_large) out[b * R_LARGE + rc + r] = sum;
        else          out[B_LARGE * R_LARGE + b * R_SMALL + r] = sum;
    }
    __syncthreads();                       // wsum free for next pass
}

__global__ __launch_bounds__(256, 3)
void lora_kernel(const float* __restrict__ x,
                 const int*   __restrict__ wl,
                 const int*   __restrict__ ws,
                 const float* __restrict__ A_large,
                 const float* __restrict__ A_small,
                 float*       __restrict__ out)
{
    __shared__ float wsum[8 * 4 * 16];  // 2 KB: per-warp partials
    __shared__ int   s_list[256];
    __shared__ int   s_cnt;

    const int c    = blockIdx.x;        // 0..639
    const int tid  = threadIdx.x;       // 0..255
    const int warp = tid >> 5;
    const int lane = tid & 31;

    const bool is_large = (c < N_ADAPT * 4);
    int w, rc = 0;
    const float* A;
    if (is_large) {
        w  = c >> 2;
        rc = (c & 3) * 16;
        A  = A_large + (size_t)w * D_DIM * R_LARGE + rc;
    } else {
        w = c - N_ADAPT * 4;
        A = A_small + (size_t)w * D_DIM * R_SMALL;
    }

    // ---- inline bucketing: find samples using adapter w ----
    if (tid == 0) s_cnt = 0;
    __syncthreads();
    const int wv = is_large ? wl[tid] : ws[tid];
    if (wv == w) s_list[atomicAdd(&s_cnt, 1)] = tid;
    __syncthreads();
    const int cnt = s_cnt;
    if (cnt == 0) return;               // unused adapter: no streaming

    int g = 0;
    while (g < cnt) {
        const int rem = cnt - g;
        int bidx[4];
        const int take = (rem >= 3) ? ((rem >= 4) ? 4 : 3) : rem;
        #pragma unroll
        for (int s = 0; s < 4; ++s) bidx[s] = (s < take) ? s_list[g + s] : 0;

        if (rem >= 3) {
            do_pass<4>(is_large, A, x, bidx, take, rc, wsum, out, warp, lane, tid);
        } else if (rem == 2) {
            do_pass<2>(is_large, A, x, bidx, 2, rc, wsum, out, warp, lane, tid);
        } else {
            do_pass<1>(is_large, A, x, bidx, 1, rc, wsum, out, warp, lane, tid);
        }
        g += take;
    }
}

extern "C" void kernel_launch(void* const* d_in, const int* in_sizes, int n_in,
                              void* d_out, int out_size)
{
    const float* x      = nullptr;
    const float* Alarge = nullptr;
    const float* Asmall = nullptr;
    const int*   widl   = nullptr;
    const int*   widsm  = nullptr;

    for (int i = 0; i < n_in; ++i) {
        const int sz = in_sizes[i];
        if (sz == 512 * D_DIM)                x      = (const float*)d_in[i];
        else if (sz == 128 * D_DIM * R_LARGE) Alarge = (const float*)d_in[i];
        else if (sz == 128 * D_DIM * R_SMALL) Asmall = (const float*)d_in[i];
        else if (sz == 256) { if (!widl) widl = (const int*)d_in[i];
                              else       widsm = (const int*)d_in[i]; }
    }

    float* out = (float*)d_out;
    lora_kernel<<<N_ADAPT * 4 + N_ADAPT, 256>>>(x, widl, widsm, Alarge, Asmall, out);
}